// round 13
// baseline (speedup 1.0000x reference)
#include <cuda_runtime.h>
#include <cuda_fp16.h>

// Problem constants
#define B_   2
#define T_   8
#define BT_  16
#define NQ_  128
#define NK_  128
#define DIN_ 64
#define DOUT_ 256
#define DP_  128       // d-pairs total (DOUT_/2)
// MUFU phase: d in [0,160) = dp in [0,80), 2 chunks of 40 dp
#define MCH_ 40        // dp per MUFU chunk
#define P16_ 44        // k16 row pitch in WORDS (44%4==0 align, 44%32=12 -> conflict-free LDS.128)
// Identity phase: d in [160,256), 3 chunks of 32 d
#define ICH_ 32        // d per identity chunk
#define PT_  36        // kt row pitch in words (36%32==4 -> conflict-free LDS.128)
#define DSPLIT_ 160    // d boundary between phases

// Device-global scratch
__device__ __half2 g_Qh[B_ * NQ_ * DP_];      // raw proj Q, half2 (MUFU path)
__device__ __half2 g_Kh[BT_ * NK_ * DP_];     // raw proj K, half2 (MUFU path)
__device__ float   g_Qt[B_ * NQ_ * DOUT_];    // tanh(proj Q), fp32 (identity path)
__device__ float   g_Kt[BT_ * NK_ * DOUT_];   // tanh(proj K), fp32 (identity path)

__device__ __forceinline__ __half2 h2tanh_mufu(__half2 x) {
    __half2 r;
    asm("tanh.approx.f16x2 %0, %1;"
        : "=r"(*reinterpret_cast<unsigned*>(&r))
        : "r"(*reinterpret_cast<unsigned*>(&x)));
    return r;
}
__device__ __forceinline__ float ftanh(float x) {
    float r;
    asm("tanh.approx.f32 %0, %1;" : "=f"(r) : "f"(x));
    return r;
}

// Exact tanh addition identity, FMA-pipe only:
//   tanh(q+k) = (tq+tk) * rcp(1+tq*tk)
// rcp via magic seed + 2 Newton (den in (0,2): always positive normal;
// seed err ~5% -> 0.25% -> 6e-6 after 2 iterations).
#define IDENT_ACC(tq, tk, vd, acc) do {                                   \
    const float den_ = fmaf((tq), (tk), 1.0f);                            \
    const float num_ = (tq) + (tk);                                       \
    float y_ = __int_as_float(0x7EF311C3 - __float_as_int(den_));         \
    y_ = y_ * fmaf(-den_, y_, 2.0f);                                      \
    y_ = y_ * fmaf(-den_, y_, 2.0f);                                      \
    (acc) = fmaf((vd), num_ * y_, (acc));                                 \
} while (0)

// ---------------------------------------------------------------------------
// Kernel 1: projections (fp32 math), dual-format output (unchanged from R12).
// ---------------------------------------------------------------------------
__global__ void __launch_bounds__(512, 1) proj_kernel(
    const float* __restrict__ query, const float* __restrict__ keys,
    const float* __restrict__ Wq,    const float* __restrict__ Wk,
    const float* __restrict__ bk)
{
    __shared__ float w_sh[32][DOUT_];
    __shared__ float in_sh[16][DIN_];

    const int blk = blockIdx.x;             // 0..143 (16 Q, 128 K)
    const bool isQ = (blk < 16);
    const int r0 = (isQ ? blk : (blk - 16)) * 16;
    const float* __restrict__ in = isQ ? query : keys;
    const float* __restrict__ W  = isQ ? Wq    : Wk;
    __half2* __restrict__ outh   = isQ ? g_Qh  : g_Kh;
    float* __restrict__ outt     = isQ ? g_Qt  : g_Kt;

    const int tid = threadIdx.x;
    const int cg = tid & 63;
    const int rg = tid >> 6;
    const int row0 = rg * 2, row1 = rg * 2 + 1;

    if (tid < 256) {
        const int r = tid >> 4, s = tid & 15;
        *(float4*)&in_sh[r][s * 4] =
            *(const float4*)(in + (size_t)(r0 + r) * DIN_ + s * 4);
    }

    float4 bias = make_float4(0.f, 0.f, 0.f, 0.f);
    if (!isQ) bias = *(const float4*)(bk + cg * 4);
    float4 acc0 = bias, acc1 = bias;

#pragma unroll 1
    for (int kc = 0; kc < 2; kc++) {
        __syncthreads();
#pragma unroll
        for (int j = 0; j < 4; j++) {
            const int f4 = tid + j * 512;
            *(float4*)&w_sh[0][f4 * 4] =
                *(const float4*)(W + (size_t)(kc * 32) * DOUT_ + f4 * 4);
        }
        __syncthreads();

#pragma unroll 4
        for (int i = 0; i < 32; i++) {
            const float4 wv = *(const float4*)&w_sh[i][cg * 4];
            const float x0 = in_sh[row0][kc * 32 + i];
            const float x1 = in_sh[row1][kc * 32 + i];
            acc0.x = fmaf(x0, wv.x, acc0.x);
            acc0.y = fmaf(x0, wv.y, acc0.y);
            acc0.z = fmaf(x0, wv.z, acc0.z);
            acc0.w = fmaf(x0, wv.w, acc0.w);
            acc1.x = fmaf(x1, wv.x, acc1.x);
            acc1.y = fmaf(x1, wv.y, acc1.y);
            acc1.z = fmaf(x1, wv.z, acc1.z);
            acc1.w = fmaf(x1, wv.w, acc1.w);
        }
    }

    {
        __half2 p0 = __floats2half2_rn(acc0.x, acc0.y);
        __half2 p1 = __floats2half2_rn(acc0.z, acc0.w);
        __half2* dst = outh + (size_t)(r0 + row0) * DP_ + cg * 2;
        dst[0] = p0; dst[1] = p1;
    }
    {
        __half2 p0 = __floats2half2_rn(acc1.x, acc1.y);
        __half2 p1 = __floats2half2_rn(acc1.z, acc1.w);
        __half2* dst = outh + (size_t)(r0 + row1) * DP_ + cg * 2;
        dst[0] = p0; dst[1] = p1;
    }
    {
        float4 t = make_float4(ftanh(acc0.x), ftanh(acc0.y),
                               ftanh(acc0.z), ftanh(acc0.w));
        *(float4*)&outt[(size_t)(r0 + row0) * DOUT_ + cg * 4] = t;
    }
    {
        float4 t = make_float4(ftanh(acc1.x), ftanh(acc1.y),
                               ftanh(acc1.z), ftanh(acc1.w));
        *(float4*)&outt[(size_t)(r0 + row1) * DOUT_ + cg * 4] = t;
    }
}

// ---------------------------------------------------------------------------
// Kernel 2: d-split hybrid scores + fused softmax.
// Grid 256 x 256 thr. Warp w -> q row q0+w; lane l -> nk {l,l+32,l+64,l+96}.
// Phase 1 (d 0..159): f16x2 MUFU tanh, 2 chunks of 40 dp (pitch-44).
// Phase 2 (d 160..255): exact FMA identity, 3 chunks of 32 d (pitch-36).
// MUFU ~30.7K cyc/SMSP, FMA ~29.5K: balanced dual saturation.
// ---------------------------------------------------------------------------
__global__ void __launch_bounds__(256, 2) attn_kernel(
    const float* __restrict__ v, float* __restrict__ out)
{
    __shared__ unsigned k16w[NK_ * P16_];    // 22.5 KB (40 dp chunk, pitch 44)
    __shared__ float    kt_sh[NK_ * PT_];    // 18.4 KB (32 d chunk, pitch 36)
    __shared__ unsigned q16_sh[8][MCH_];     // 1.25 KB
    __shared__ float    qt_sh[8][ICH_];      // 1 KB
    __shared__ unsigned v16_sh[MCH_];        // 160 B
    __shared__ float    vt_sh[ICH_];         // 128 B

    const int bt = blockIdx.x >> 4;
    const int q0 = (blockIdx.x & 15) << 3;
    const int b  = bt >> 3;

    const int tid  = threadIdx.x;
    const int w    = tid >> 5;
    const int lane = tid & 31;

    const __half2* __restrict__ khbase = g_Kh + (size_t)(bt * NK_) * DP_;
    const __half2* __restrict__ qhbase = g_Qh + (size_t)(b * NQ_ + q0) * DP_;
    const float*   __restrict__ ktbase = g_Kt + (size_t)(bt * NK_) * DOUT_;
    const float*   __restrict__ qtbase = g_Qt + (size_t)(b * NQ_ + q0) * DOUT_;

    float acc0 = 0.f, acc1 = 0.f, acc2 = 0.f, acc3 = 0.f;

    // ======== Phase 1: f16x2 MUFU tanh, d in [0,160) ========
#pragma unroll 1
    for (int c = 0; c < 2; c++) {
        const int dp0 = c * MCH_;

        // Stage k16: 128 rows x 10 uint4 (1280 uint4, 5/thread)
#pragma unroll
        for (int i = 0; i < 5; i++) {
            const int e = tid + i * 256;
            const int nk = e / 10, s = e % 10;
            uint4 t = *(const uint4*)(khbase + (size_t)nk * DP_ + dp0 + s * 4);
            *(uint4*)&k16w[nk * P16_ + s * 4] = t;
        }
        // Stage q16: 8 rows x 10 uint4
        if (tid < 80) {
            const int r = tid / 10, s = tid % 10;
            *(uint4*)&q16_sh[r][s * 4] =
                *(const uint4*)(qhbase + (size_t)r * DP_ + dp0 + s * 4);
        }
        // Stage v16 (fp32 -> half2)
        if (tid >= 128 && tid < 128 + MCH_) {
            const int i = tid - 128;
            float2 vv = *(const float2*)(v + 2 * (dp0 + i));
            __half2 hh = __floats2half2_rn(vv.x, vv.y);
            v16_sh[i] = *reinterpret_cast<unsigned*>(&hh);
        }
        __syncthreads();

        const unsigned* __restrict__ k0p = &k16w[(lane      ) * P16_];
        const unsigned* __restrict__ k1p = &k16w[(lane + 32 ) * P16_];
        const unsigned* __restrict__ k2p = &k16w[(lane + 64 ) * P16_];
        const unsigned* __restrict__ k3p = &k16w[(lane + 96 ) * P16_];

#pragma unroll 5
        for (int dp8 = 0; dp8 < MCH_; dp8 += 8) {
            unsigned k0[8], k1[8], k2[8], k3[8], qr[8], vr[8];
            *(uint4*)&k0[0] = *(const uint4*)(k0p + dp8);
            *(uint4*)&k0[4] = *(const uint4*)(k0p + dp8 + 4);
            *(uint4*)&k1[0] = *(const uint4*)(k1p + dp8);
            *(uint4*)&k1[4] = *(const uint4*)(k1p + dp8 + 4);
            *(uint4*)&k2[0] = *(const uint4*)(k2p + dp8);
            *(uint4*)&k2[4] = *(const uint4*)(k2p + dp8 + 4);
            *(uint4*)&k3[0] = *(const uint4*)(k3p + dp8);
            *(uint4*)&k3[4] = *(const uint4*)(k3p + dp8 + 4);
            *(uint4*)&qr[0] = *(const uint4*)&q16_sh[w][dp8];
            *(uint4*)&qr[4] = *(const uint4*)&q16_sh[w][dp8 + 4];
            *(uint4*)&vr[0] = *(const uint4*)&v16_sh[dp8];
            *(uint4*)&vr[4] = *(const uint4*)&v16_sh[dp8 + 4];

            __half2 h0 = __float2half2_rn(0.f);
            __half2 h1 = h0, h2 = h0, h3 = h0;
#pragma unroll
            for (int j = 0; j < 8; j++) {
                const __half2 qp = *reinterpret_cast<const __half2*>(&qr[j]);
                const __half2 vp = *reinterpret_cast<const __half2*>(&vr[j]);
                __half2 t0 = h2tanh_mufu(__hadd2(qp, *reinterpret_cast<const __half2*>(&k0[j])));
                __half2 t1 = h2tanh_mufu(__hadd2(qp, *reinterpret_cast<const __half2*>(&k1[j])));
                __half2 t2 = h2tanh_mufu(__hadd2(qp, *reinterpret_cast<const __half2*>(&k2[j])));
                __half2 t3 = h2tanh_mufu(__hadd2(qp, *reinterpret_cast<const __half2*>(&k3[j])));
                h0 = __hfma2(vp, t0, h0);
                h1 = __hfma2(vp, t1, h1);
                h2 = __hfma2(vp, t2, h2);
                h3 = __hfma2(vp, t3, h3);
            }
            float2 f0 = __half22float2(h0);
            float2 f1 = __half22float2(h1);
            float2 f2 = __half22float2(h2);
            float2 f3 = __half22float2(h3);
            acc0 += f0.x + f0.y;
            acc1 += f1.x + f1.y;
            acc2 += f2.x + f2.y;
            acc3 += f3.x + f3.y;
        }
        __syncthreads();
    }

    // ======== Phase 2: exact FMA identity, d in [160,256) ========
#pragma unroll 1
    for (int c = 0; c < 3; c++) {
        const int d0 = DSPLIT_ + c * ICH_;

        // Stage kt: 128 rows x 8 float4 (1024 float4, 4/thread), pitch 36
#pragma unroll
        for (int i = 0; i < 4; i++) {
            const int e = tid + i * 256;
            const int nk = e >> 3, s = e & 7;
            float4 t = *(const float4*)(ktbase + (size_t)nk * DOUT_ + d0 + s * 4);
            *(float4*)&kt_sh[nk * PT_ + s * 4] = t;
        }
        // Stage qt: 8 rows x 8 float4
        if (tid < 64) {
            const int r = tid >> 3, s = tid & 7;
            *(float4*)&qt_sh[r][s * 4] =
                *(const float4*)(qtbase + (size_t)r * DOUT_ + d0 + s * 4);
        }
        // Stage vt
        if (tid >= 128 && tid < 136) {
            const int s = tid - 128;
            *(float4*)&vt_sh[s * 4] = *(const float4*)(v + d0 + s * 4);
        }
        __syncthreads();

        const float* __restrict__ kAp = &kt_sh[(lane      ) * PT_];
        const float* __restrict__ kBp = &kt_sh[(lane + 32 ) * PT_];
        const float* __restrict__ kCp = &kt_sh[(lane + 64 ) * PT_];
        const float* __restrict__ kDp = &kt_sh[(lane + 96 ) * PT_];

#pragma unroll 4
        for (int d4 = 0; d4 < ICH_; d4 += 4) {
            float4 kA = *(const float4*)(kAp + d4);
            float4 kB = *(const float4*)(kBp + d4);
            float4 kC = *(const float4*)(kCp + d4);
            float4 kD = *(const float4*)(kDp + d4);
            float4 qv = *(const float4*)&qt_sh[w][d4];
            float4 vv = *(const float4*)&vt_sh[d4];

            IDENT_ACC(qv.x, kA.x, vv.x, acc0);
            IDENT_ACC(qv.x, kB.x, vv.x, acc1);
            IDENT_ACC(qv.x, kC.x, vv.x, acc2);
            IDENT_ACC(qv.x, kD.x, vv.x, acc3);

            IDENT_ACC(qv.y, kA.y, vv.y, acc0);
            IDENT_ACC(qv.y, kB.y, vv.y, acc1);
            IDENT_ACC(qv.y, kC.y, vv.y, acc2);
            IDENT_ACC(qv.y, kD.y, vv.y, acc3);

            IDENT_ACC(qv.z, kA.z, vv.z, acc0);
            IDENT_ACC(qv.z, kB.z, vv.z, acc1);
            IDENT_ACC(qv.z, kC.z, vv.z, acc2);
            IDENT_ACC(qv.z, kD.z, vv.z, acc3);

            IDENT_ACC(qv.w, kA.w, vv.w, acc0);
            IDENT_ACC(qv.w, kB.w, vv.w, acc1);
            IDENT_ACC(qv.w, kC.w, vv.w, acc2);
            IDENT_ACC(qv.w, kD.w, vv.w, acc3);
        }
        __syncthreads();
    }

    // Fused softmax over nk (warp owns the full 128-wide row)
    float m = fmaxf(fmaxf(acc0, acc1), fmaxf(acc2, acc3));
#pragma unroll
    for (int o = 16; o > 0; o >>= 1)
        m = fmaxf(m, __shfl_xor_sync(0xffffffffu, m, o));

    const float e0 = __expf(acc0 - m);
    const float e1 = __expf(acc1 - m);
    const float e2 = __expf(acc2 - m);
    const float e3 = __expf(acc3 - m);
    float ssum = e0 + e1 + e2 + e3;
#pragma unroll
    for (int o = 16; o > 0; o >>= 1)
        ssum += __shfl_xor_sync(0xffffffffu, ssum, o);

    const float rinv = 1.0f / ssum;

    float* __restrict__ orow = out + (size_t)(bt * NQ_ + q0 + w) * NK_;
    orow[lane      ] = e0 * rinv;
    orow[lane + 32 ] = e1 * rinv;
    orow[lane + 64 ] = e2 * rinv;
    orow[lane + 96 ] = e3 * rinv;
}

// ---------------------------------------------------------------------------
extern "C" void kernel_launch(void* const* d_in, const int* in_sizes, int n_in,
                              void* d_out, int out_size)
{
    const float* query = (const float*)d_in[0];
    const float* keys  = (const float*)d_in[1];
    const float* Wq    = (const float*)d_in[2];
    const float* Wk    = (const float*)d_in[3];
    const float* bk    = (const float*)d_in[4];
    const float* v     = (const float*)d_in[5];
    float* out = (float*)d_out;

    proj_kernel<<<144, 512>>>(query, keys, Wq, Wk, bk);
    attn_kernel<<<256, 256>>>(v, out);
}

// round 14
// speedup vs baseline: 1.1405x; 1.1405x over previous
#include <cuda_runtime.h>
#include <cuda_fp16.h>

// Problem constants
#define B_   2
#define T_   8
#define BT_  16
#define NQ_  128
#define NK_  128
#define DIN_ 64
#define DOUT_ 256
#define DP_  128     // d-pairs total (DOUT_/2)
#define DPC2_ 32     // d-pairs per staged chunk (4 chunks of 64 d)
#define P16_ 33      // k16 row pitch in half2 words (odd -> conflict-free LDS.32)
#define PT_  68      // kt row pitch in float words (68/4=17 odd -> conflict-free LDS.128)

// Device-global scratch
__device__ __half2 g_Qh[B_ * NQ_ * DP_];      // raw proj Q, half2 (MUFU path)
__device__ __half2 g_Kh[BT_ * NK_ * DP_];     // raw proj K, half2 (MUFU path)
__device__ float   g_Qt[B_ * NQ_ * DOUT_];    // tanh(proj Q), fp32 (identity path)
__device__ float   g_Kt[BT_ * NK_ * DOUT_];   // tanh(proj K), fp32 (identity path)

__device__ __forceinline__ __half2 h2tanh_mufu(__half2 x) {
    __half2 r;
    asm("tanh.approx.f16x2 %0, %1;"
        : "=r"(*reinterpret_cast<unsigned*>(&r))
        : "r"(*reinterpret_cast<unsigned*>(&x)));
    return r;
}
__device__ __forceinline__ float ftanh(float x) {
    float r;
    asm("tanh.approx.f32 %0, %1;" : "=f"(r) : "f"(x));
    return r;
}

// Exact tanh addition identity, FMA-pipe only (8 FMA-class ops):
//   tanh(q+k) = (tq+tk) * rcp(1+tq*tk);  den in (0,2) always positive normal.
// rcp: magic seed (~3% err) + 2 Newton -> ~1.3e-6.
#define IDENT_ACC(tq, tk, vd, acc) do {                                   \
    const float den_ = fmaf((tq), (tk), 1.0f);                            \
    const float num_ = (tq) + (tk);                                       \
    float y_ = __int_as_float(0x7EF311C3 - __float_as_int(den_));         \
    y_ = y_ * fmaf(-den_, y_, 2.0f);                                      \
    y_ = y_ * fmaf(-den_, y_, 2.0f);                                      \
    (acc) = fmaf((vd), num_ * y_, (acc));                                 \
} while (0)

// ---------------------------------------------------------------------------
// Kernel 1: projections (fp32 math), dual-format output (unchanged from R12).
// ---------------------------------------------------------------------------
__global__ void __launch_bounds__(512, 1) proj_kernel(
    const float* __restrict__ query, const float* __restrict__ keys,
    const float* __restrict__ Wq,    const float* __restrict__ Wk,
    const float* __restrict__ bk)
{
    __shared__ float w_sh[32][DOUT_];
    __shared__ float in_sh[16][DIN_];

    const int blk = blockIdx.x;             // 0..143 (16 Q, 128 K)
    const bool isQ = (blk < 16);
    const int r0 = (isQ ? blk : (blk - 16)) * 16;
    const float* __restrict__ in = isQ ? query : keys;
    const float* __restrict__ W  = isQ ? Wq    : Wk;
    __half2* __restrict__ outh   = isQ ? g_Qh  : g_Kh;
    float* __restrict__ outt     = isQ ? g_Qt  : g_Kt;

    const int tid = threadIdx.x;
    const int cg = tid & 63;
    const int rg = tid >> 6;
    const int row0 = rg * 2, row1 = rg * 2 + 1;

    if (tid < 256) {
        const int r = tid >> 4, s = tid & 15;
        *(float4*)&in_sh[r][s * 4] =
            *(const float4*)(in + (size_t)(r0 + r) * DIN_ + s * 4);
    }

    float4 bias = make_float4(0.f, 0.f, 0.f, 0.f);
    if (!isQ) bias = *(const float4*)(bk + cg * 4);
    float4 acc0 = bias, acc1 = bias;

#pragma unroll 1
    for (int kc = 0; kc < 2; kc++) {
        __syncthreads();
#pragma unroll
        for (int j = 0; j < 4; j++) {
            const int f4 = tid + j * 512;
            *(float4*)&w_sh[0][f4 * 4] =
                *(const float4*)(W + (size_t)(kc * 32) * DOUT_ + f4 * 4);
        }
        __syncthreads();

#pragma unroll 4
        for (int i = 0; i < 32; i++) {
            const float4 wv = *(const float4*)&w_sh[i][cg * 4];
            const float x0 = in_sh[row0][kc * 32 + i];
            const float x1 = in_sh[row1][kc * 32 + i];
            acc0.x = fmaf(x0, wv.x, acc0.x);
            acc0.y = fmaf(x0, wv.y, acc0.y);
            acc0.z = fmaf(x0, wv.z, acc0.z);
            acc0.w = fmaf(x0, wv.w, acc0.w);
            acc1.x = fmaf(x1, wv.x, acc1.x);
            acc1.y = fmaf(x1, wv.y, acc1.y);
            acc1.z = fmaf(x1, wv.z, acc1.z);
            acc1.w = fmaf(x1, wv.w, acc1.w);
        }
    }

    {
        __half2 p0 = __floats2half2_rn(acc0.x, acc0.y);
        __half2 p1 = __floats2half2_rn(acc0.z, acc0.w);
        __half2* dst = outh + (size_t)(r0 + row0) * DP_ + cg * 2;
        dst[0] = p0; dst[1] = p1;
    }
    {
        __half2 p0 = __floats2half2_rn(acc1.x, acc1.y);
        __half2 p1 = __floats2half2_rn(acc1.z, acc1.w);
        __half2* dst = outh + (size_t)(r0 + row1) * DP_ + cg * 2;
        dst[0] = p0; dst[1] = p1;
    }
    {
        float4 t = make_float4(ftanh(acc0.x), ftanh(acc0.y),
                               ftanh(acc0.z), ftanh(acc0.w));
        *(float4*)&outt[(size_t)(r0 + row0) * DOUT_ + cg * 4] = t;
    }
    {
        float4 t = make_float4(ftanh(acc1.x), ftanh(acc1.y),
                               ftanh(acc1.z), ftanh(acc1.w));
        *(float4*)&outt[(size_t)(r0 + row1) * DOUT_ + cg * 4] = t;
    }
}

// ---------------------------------------------------------------------------
// Kernel 2: warp-mixed hybrid scores + fused softmax.
// Grid 256 x 256 thr. Warp w -> q row q0+w; lane l -> nk {l,l+32,l+64,l+96}.
// Warps 0-3: streams A,B,C = f16x2 MUFU tanh; D = FMA identity (f=0.75)
// Warps 4-7: streams A,B   = f16x2 MUFU tanh; C,D = FMA identity (f=0.5)
// SMSP sees one of each (w%4) -> average f=0.625: MUFU 26.6K cyc, FMA ~27K
// -> balanced dual-pipe saturation. Both paths interleave in one stream
// per warp (R13 lesson: phase-separated pipes serialize).
// ---------------------------------------------------------------------------
__global__ void __launch_bounds__(256, 2) attn_kernel(
    const float* __restrict__ v, float* __restrict__ out)
{
    __shared__ unsigned k16_sh[96 * P16_];  // 12.7 KB: nk 0..95 raw half2
    __shared__ float    kt_sh[64 * PT_];    // 17.4 KB: nk 64..127 tanh'd fp32
    __shared__ unsigned q16_sh[8][DPC2_];   // 1 KB
    __shared__ float    qt_sh[8][2 * DPC2_];// 2 KB
    __shared__ unsigned v16_sh[DPC2_];      // 128 B
    __shared__ float    vt_sh[2 * DPC2_];   // 256 B

    const int bt = blockIdx.x >> 4;
    const int q0 = (blockIdx.x & 15) << 3;
    const int b  = bt >> 3;

    const int tid  = threadIdx.x;
    const int w    = tid >> 5;
    const int lane = tid & 31;

    const __half2* __restrict__ khbase = g_Kh + (size_t)(bt * NK_) * DP_;
    const __half2* __restrict__ qhbase = g_Qh + (size_t)(b * NQ_ + q0) * DP_;
    const float*   __restrict__ ktbase = g_Kt + (size_t)(bt * NK_ + 64) * DOUT_;
    const float*   __restrict__ qtbase = g_Qt + (size_t)(b * NQ_ + q0) * DOUT_;

    float acc0 = 0.f, acc1 = 0.f, acc2 = 0.f, acc3 = 0.f;

#pragma unroll 1
    for (int c = 0; c < DP_ / DPC2_; c++) {
        const int d0dp = c * DPC2_;          // dp offset
        const int d0   = c * 2 * DPC2_;      // d offset

        // Stage k16: 96 rows x 8 uint4 (3/thread); scalar STS (odd pitch)
#pragma unroll
        for (int e = tid; e < 96 * 8; e += 256) {
            const int nk = e >> 3, s = e & 7;
            uint4 t = *(const uint4*)(khbase + (size_t)nk * DP_ + d0dp + s * 4);
            unsigned* dst = &k16_sh[nk * P16_ + s * 4];
            dst[0] = t.x; dst[1] = t.y; dst[2] = t.z; dst[3] = t.w;
        }
        // Stage kt: 64 rows (nk 64..127) x 16 float4 (4/thread), pitch 68
#pragma unroll
        for (int e = tid; e < 64 * 16; e += 256) {
            const int nk = e >> 4, s = e & 15;
            float4 t = *(const float4*)(ktbase + (size_t)nk * DOUT_ + d0 + s * 4);
            *(float4*)&kt_sh[nk * PT_ + s * 4] = t;
        }
        // Stage q16: 8 rows x 8 uint4
        if (tid < 64) {
            const int r = tid >> 3, s = tid & 7;
            *(uint4*)&q16_sh[r][s * 4] =
                *(const uint4*)(qhbase + (size_t)r * DP_ + d0dp + s * 4);
        }
        // Stage qt: 8 rows x 16 float4
        if (tid >= 64 && tid < 192) {
            const int e = tid - 64;
            const int r = e >> 4, s = e & 15;
            *(float4*)&qt_sh[r][s * 4] =
                *(const float4*)(qtbase + (size_t)r * DOUT_ + d0 + s * 4);
        }
        // Stage v16 (fp32 -> half2) and vt (fp32)
        if (tid >= 192 && tid < 224) {
            const int i = tid - 192;
            float2 vv = *(const float2*)(v + d0 + 2 * i);
            __half2 hh = __floats2half2_rn(vv.x, vv.y);
            v16_sh[i] = *reinterpret_cast<unsigned*>(&hh);
        }
        if (tid >= 224 && tid < 240) {
            const int s = tid - 224;
            *(float4*)&vt_sh[s * 4] = *(const float4*)(v + d0 + s * 4);
        }
        __syncthreads();

        const unsigned* __restrict__ k0p = &k16_sh[(lane      ) * P16_];
        const unsigned* __restrict__ k1p = &k16_sh[(lane + 32 ) * P16_];
        const unsigned* __restrict__ k2p = &k16_sh[(lane + 64 ) * P16_];
        const float*    __restrict__ kCp = &kt_sh[(lane      ) * PT_];  // nk l+64
        const float*    __restrict__ kDp = &kt_sh[(lane + 32 ) * PT_];  // nk l+96

        if (w < 4) {
            // ---- f = 0.75: streams A,B,C MUFU; D identity ----
#pragma unroll 2
            for (int dp8 = 0; dp8 < DPC2_; dp8 += 8) {
                uint4 qa  = *(const uint4*)&q16_sh[w][dp8];
                uint4 qb4 = *(const uint4*)&q16_sh[w][dp8 + 4];
                uint4 va  = *(const uint4*)&v16_sh[dp8];
                uint4 vb4 = *(const uint4*)&v16_sh[dp8 + 4];
                unsigned qr[8] = {qa.x, qa.y, qa.z, qa.w, qb4.x, qb4.y, qb4.z, qb4.w};
                unsigned vr[8] = {va.x, va.y, va.z, va.w, vb4.x, vb4.y, vb4.z, vb4.w};

                __half2 h0 = __float2half2_rn(0.f);
                __half2 h1 = h0, h2 = h0;
#pragma unroll
                for (int j = 0; j < 8; j++) {
                    const int dp = dp8 + j;
                    const __half2 qp = *reinterpret_cast<const __half2*>(&qr[j]);
                    const __half2 vp = *reinterpret_cast<const __half2*>(&vr[j]);
                    __half2 t0 = h2tanh_mufu(__hadd2(qp, *reinterpret_cast<const __half2*>(&k0p[dp])));
                    __half2 t1 = h2tanh_mufu(__hadd2(qp, *reinterpret_cast<const __half2*>(&k1p[dp])));
                    __half2 t2 = h2tanh_mufu(__hadd2(qp, *reinterpret_cast<const __half2*>(&k2p[dp])));
                    h0 = __hfma2(vp, t0, h0);
                    h1 = __hfma2(vp, t1, h1);
                    h2 = __hfma2(vp, t2, h2);
                }
                float2 f0 = __half22float2(h0);
                float2 f1 = __half22float2(h1);
                float2 f2 = __half22float2(h2);
                acc0 += f0.x + f0.y;
                acc1 += f1.x + f1.y;
                acc2 += f2.x + f2.y;

                const int dd = 2 * dp8;
#pragma unroll
                for (int p4 = 0; p4 < 4; p4++) {
                    const float4 kD = *(const float4*)(kDp + dd + p4 * 4);
                    const float4 qD = *(const float4*)&qt_sh[w][dd + p4 * 4];
                    const float4 vD = *(const float4*)&vt_sh[dd + p4 * 4];
                    IDENT_ACC(qD.x, kD.x, vD.x, acc3);
                    IDENT_ACC(qD.y, kD.y, vD.y, acc3);
                    IDENT_ACC(qD.z, kD.z, vD.z, acc3);
                    IDENT_ACC(qD.w, kD.w, vD.w, acc3);
                }
            }
        } else {
            // ---- f = 0.5: streams A,B MUFU; C,D identity ----
#pragma unroll 2
            for (int dp8 = 0; dp8 < DPC2_; dp8 += 8) {
                uint4 qa  = *(const uint4*)&q16_sh[w][dp8];
                uint4 qb4 = *(const uint4*)&q16_sh[w][dp8 + 4];
                uint4 va  = *(const uint4*)&v16_sh[dp8];
                uint4 vb4 = *(const uint4*)&v16_sh[dp8 + 4];
                unsigned qr[8] = {qa.x, qa.y, qa.z, qa.w, qb4.x, qb4.y, qb4.z, qb4.w};
                unsigned vr[8] = {va.x, va.y, va.z, va.w, vb4.x, vb4.y, vb4.z, vb4.w};

                __half2 h0 = __float2half2_rn(0.f);
                __half2 h1 = h0;
#pragma unroll
                for (int j = 0; j < 8; j++) {
                    const int dp = dp8 + j;
                    const __half2 qp = *reinterpret_cast<const __half2*>(&qr[j]);
                    const __half2 vp = *reinterpret_cast<const __half2*>(&vr[j]);
                    __half2 t0 = h2tanh_mufu(__hadd2(qp, *reinterpret_cast<const __half2*>(&k0p[dp])));
                    __half2 t1 = h2tanh_mufu(__hadd2(qp, *reinterpret_cast<const __half2*>(&k1p[dp])));
                    h0 = __hfma2(vp, t0, h0);
                    h1 = __hfma2(vp, t1, h1);
                }
                float2 f0 = __half22float2(h0);
                float2 f1 = __half22float2(h1);
                acc0 += f0.x + f0.y;
                acc1 += f1.x + f1.y;

                const int dd = 2 * dp8;
#pragma unroll
                for (int p4 = 0; p4 < 4; p4++) {
                    const float4 kC = *(const float4*)(kCp + dd + p4 * 4);
                    const float4 kD = *(const float4*)(kDp + dd + p4 * 4);
                    const float4 qD = *(const float4*)&qt_sh[w][dd + p4 * 4];
                    const float4 vD = *(const float4*)&vt_sh[dd + p4 * 4];
                    IDENT_ACC(qD.x, kC.x, vD.x, acc2);
                    IDENT_ACC(qD.y, kC.y, vD.y, acc2);
                    IDENT_ACC(qD.z, kC.z, vD.z, acc2);
                    IDENT_ACC(qD.w, kC.w, vD.w, acc2);
                    IDENT_ACC(qD.x, kD.x, vD.x, acc3);
                    IDENT_ACC(qD.y, kD.y, vD.y, acc3);
                    IDENT_ACC(qD.z, kD.z, vD.z, acc3);
                    IDENT_ACC(qD.w, kD.w, vD.w, acc3);
                }
            }
        }
        __syncthreads();
    }

    // Fused softmax over nk (warp owns the full 128-wide row)
    float m = fmaxf(fmaxf(acc0, acc1), fmaxf(acc2, acc3));
#pragma unroll
    for (int o = 16; o > 0; o >>= 1)
        m = fmaxf(m, __shfl_xor_sync(0xffffffffu, m, o));

    const float e0 = __expf(acc0 - m);
    const float e1 = __expf(acc1 - m);
    const float e2 = __expf(acc2 - m);
    const float e3 = __expf(acc3 - m);
    float ssum = e0 + e1 + e2 + e3;
#pragma unroll
    for (int o = 16; o > 0; o >>= 1)
        ssum += __shfl_xor_sync(0xffffffffu, ssum, o);

    const float rinv = 1.0f / ssum;

    float* __restrict__ orow = out + (size_t)(bt * NQ_ + q0 + w) * NK_;
    orow[lane      ] = e0 * rinv;
    orow[lane + 32 ] = e1 * rinv;
    orow[lane + 64 ] = e2 * rinv;
    orow[lane + 96 ] = e3 * rinv;
}

// ---------------------------------------------------------------------------
extern "C" void kernel_launch(void* const* d_in, const int* in_sizes, int n_in,
                              void* d_out, int out_size)
{
    const float* query = (const float*)d_in[0];
    const float* keys  = (const float*)d_in[1];
    const float* Wq    = (const float*)d_in[2];
    const float* Wk    = (const float*)d_in[3];
    const float* bk    = (const float*)d_in[4];
    const float* v     = (const float*)d_in[5];
    float* out = (float*)d_out;

    proj_kernel<<<144, 512>>>(query, keys, Wq, Wk, bk);
    attn_kernel<<<256, 256>>>(v, out);
}